// round 2
// baseline (speedup 1.0000x reference)
#include <cuda_runtime.h>
#include <cuda_bf16.h>

#define BATCH 16
#define LEN   2048
#define JT    16              // j-tiles per batch row
#define JTILE (LEN / JT)      // 128 j per tile
#define TPB   256
#define AR    4               // a-values register-blocked per thread
#define GAMMA 0.1f

// Scratch (no allocations allowed)
__device__ float g_xpos[BATCH][LEN];
__device__ float g_fpos[BATCH][LEN];
__device__ int   g_cnt[BATCH];
__device__ float g_partial[BATCH * JT];

// ---------------- Kernel 1: deterministic per-batch compaction of positive a's
__global__ void compact_kernel(const float* __restrict__ inp,
                               const int* __restrict__ tgt,
                               const float* __restrict__ freq) {
    int b = blockIdx.x;
    int lane = threadIdx.x;           // 32 threads = 1 warp per batch
    int base = 0;
    for (int i0 = 0; i0 < LEN; i0 += 32) {
        int i = i0 + lane;
        int t = tgt[b * LEN + i];
        unsigned m = __ballot_sync(0xffffffffu, t != 0);
        if (t != 0) {
            int pos = base + __popc(m & ((1u << lane) - 1u));
            float v = inp[b * LEN + i];
            g_xpos[b][pos] = 1.0f / (1.0f + __expf(-v));   // sigmoid
            g_fpos[b][pos] = freq[i];
        }
        base += __popc(m);
    }
    if (lane == 0) g_cnt[b] = base;
}

// ---------------- Kernel 2: pairwise loss over (compacted a) x (j tile)
__global__ __launch_bounds__(TPB) void pair_kernel(const float* __restrict__ inp,
                                                   const int* __restrict__ tgt,
                                                   const float* __restrict__ freq) {
    const int jt = blockIdx.x;
    const int b  = blockIdx.y;
    const int tid = threadIdx.x;

    __shared__ float4 tile[JTILE];    // (x_j, f_j, p_j, gamma*(1-p_j))
    __shared__ float  red[TPB];

    // cooperative j-tile load + on-the-fly sigmoid
    for (int j = tid; j < JTILE; j += TPB) {
        int jj = jt * JTILE + j;
        float v = inp[b * LEN + jj];
        float x = 1.0f / (1.0f + __expf(-v));
        float p = (float)tgt[b * LEN + jj];
        float f = freq[jj];
        tile[j] = make_float4(x, f, p, GAMMA * (1.0f - p));
    }
    __syncthreads();

    const int cnt = g_cnt[b];
    float total = 0.0f;

    for (int base = 0; base < cnt; base += TPB * AR) {
        float xa[AR], fa[AR], va[AR], acc[AR];
#pragma unroll
        for (int k = 0; k < AR; k++) {
            int ai = base + tid + k * TPB;
            bool ok = (ai < cnt);
            xa[k]  = ok ? g_xpos[b][ai] : 0.0f;
            fa[k]  = ok ? g_fpos[b][ai] : 1.0f;
            va[k]  = ok ? 1.0f : 0.0f;
            acc[k] = 0.0f;
        }
        for (int j = 0; j < JTILE; j++) {
            float4 t4 = tile[j];   // one LDS.128 reused across AR pairs
#pragma unroll
            for (int k = 0; k < AR; k++) {
                float d  = xa[k] - t4.x;                 // x_a - x_j
                float fd = fa[k] - t4.y;                 // f_a - f_j
                float s  = fa[k] + t4.y;                 // f_a + f_j  (>0)
                float r;
                asm("rcp.approx.f32 %0, %1;" : "=f"(r) : "f"(s));
                float u  = fmaxf(fd * d * r, 0.0f);      // relu(n * diff)
                float l2 = fmaxf(-d, 0.0f);              // relu(x_j - x_a), C=0
                acc[k] = fmaf(t4.z, u, fmaf(t4.w, l2, acc[k]));
            }
        }
#pragma unroll
        for (int k = 0; k < AR; k++) total += va[k] * acc[k];
    }

    // deterministic in-block tree reduction
    red[tid] = total;
    __syncthreads();
    for (int s = TPB / 2; s > 0; s >>= 1) {
        if (tid < s) red[tid] += red[tid + s];
        __syncthreads();
    }
    if (tid == 0) g_partial[b * JT + jt] = red[0];
}

// ---------------- Kernel 3: fixed-order final reduction (deterministic, no atomics)
__global__ void reduce_kernel(float* __restrict__ out, int out_size) {
    __shared__ float red[BATCH * JT];
    int tid = threadIdx.x;                  // BATCH*JT = 256 threads
    red[tid] = g_partial[tid];
    __syncthreads();
    for (int s = (BATCH * JT) / 2; s > 0; s >>= 1) {
        if (tid < s) red[tid] += red[tid + s];
        __syncthreads();
    }
    if (tid == 0) {
        float result = red[0] / (float)BATCH;
        for (int i = 0; i < out_size; i++) out[i] = result;
    }
}

extern "C" void kernel_launch(void* const* d_in, const int* in_sizes, int n_in,
                              void* d_out, int out_size) {
    const float* inp  = (const float*)d_in[0];   // [16, 2048] f32
    const int*   tgt  = (const int*)d_in[1];     // [16, 2048] i32
    const float* freq = (const float*)d_in[2];   // [2048] f32
    float* out = (float*)d_out;

    compact_kernel<<<BATCH, 32>>>(inp, tgt, freq);
    pair_kernel<<<dim3(JT, BATCH), TPB>>>(inp, tgt, freq);
    reduce_kernel<<<1, BATCH * JT>>>(out, out_size);
}

// round 4
// speedup vs baseline: 3.5814x; 3.5814x over previous
#include <cuda_runtime.h>
#include <cuda_bf16.h>

#define BATCH 16
#define LEN   2048
#define JT    37              // 37*16 = 592 = 148*4 blocks -> one even wave
#define TPB   256
#define NW    (TPB/32)        // 8 warps
#define CHUNK (LEN/NW)        // 256 elements per warp in compaction
#define KPW   (CHUNK/32)      // 8 ballot sub-iterations per warp
#define AR    4
#define GAMMA 0.1f
#define MAXM  ((LEN + JT - 1)/JT)   // 56 max j-slots per block

__device__ float g_partial[BATCH * JT];

__device__ __forceinline__ float sigmoidf(float v) {
    return 1.0f / (1.0f + __expf(-v));
}

// One block = (j-slot stride class jt, batch b).
// Phase 1: block-compacts the batch row into P(x,f) and N(x) lists in smem.
// Phase 2: gathers its strided j-slot window (slots s = jt + 37*m over the
//          concatenated [P|N] ordering -> first mP slots are P, rest N).
// Phase 3: register-blocked pair loops (PP term, PN term), block reduce.
__global__ __launch_bounds__(TPB, 4) void pair_kernel(
        const float* __restrict__ inp,
        const int*   __restrict__ tgt,
        const float* __restrict__ freq) {
    const int jt  = blockIdx.x;
    const int b   = blockIdx.y;
    const int tid = threadIdx.x;
    const int w   = tid >> 5;
    const int lane = tid & 31;

    __shared__ float  sPx[LEN];
    __shared__ float  sPf[LEN];
    __shared__ float  sNx[LEN];
    __shared__ int    s_cntP[NW];
    __shared__ float2 wPxf[MAXM];
    __shared__ float  wNx[MAXM];
    __shared__ float  red[TPB];

    const int rowoff = b * LEN;

    // ---- Pass A: per-warp ballots of positives (all loads independent, MLP=8)
    unsigned bal[KPW];
    int pc = 0;
#pragma unroll
    for (int k = 0; k < KPW; k++) {
        int i = w * CHUNK + k * 32 + lane;
        int t = tgt[rowoff + i];
        bal[k] = __ballot_sync(0xffffffffu, t != 0);
        pc += __popc(bal[k]);
    }
    if (lane == 0) s_cntP[w] = pc;
    __syncthreads();

    int prefP = 0, cp = 0;
#pragma unroll
    for (int ww = 0; ww < NW; ww++) {
        int c = s_cntP[ww];
        if (ww < w) prefP += c;
        cp += c;
    }
    const int prefN = w * CHUNK - prefP;   // negatives before this warp's chunk

    // ---- Pass B: scatter compacted values (no cross-warp coordination)
    const unsigned lt = (1u << lane) - 1u;
    int baseP = 0, baseN = 0;
#pragma unroll
    for (int k = 0; k < KPW; k++) {
        int i = w * CHUNK + k * 32 + lane;
        float x = sigmoidf(inp[rowoff + i]);
        unsigned m = bal[k];
        if ((m >> lane) & 1u) {
            int pos = prefP + baseP + __popc(m & lt);
            sPx[pos] = x;
            sPf[pos] = freq[i];
        } else {
            int pos = prefN + baseN + (lane - __popc(m & lt));
            sNx[pos] = x;
        }
        int c = __popc(m);
        baseP += c;
        baseN += 32 - c;
    }
    __syncthreads();

    // ---- Gather this block's strided j-slot window: s = jt + JT*m
    const int M = (LEN - 1 - jt) / JT + 1;
    int mP = 0;
    if (cp > jt) { mP = (cp - jt + JT - 1) / JT; if (mP > M) mP = M; }
    for (int m = tid; m < M; m += TPB) {
        int s = jt + JT * m;
        if (m < mP) wPxf[m] = make_float2(sPx[s], sPf[s]);
        else        wNx[m - mP] = sNx[s - cp];
    }
    __syncthreads();
    const int nP = mP, nN = M - mP;

    float total = 0.0f;

    // ---- Full AR=4 passes over positive a's (no guards)
    int abase = 0;
    for (; abase + TPB * AR <= cp; abase += TPB * AR) {
        float xa[AR], fa[AR], acc[AR], accN[AR];
#pragma unroll
        for (int k = 0; k < AR; k++) {
            int ai = abase + tid + k * TPB;
            xa[k] = sPx[ai]; fa[k] = sPf[ai];
            acc[k] = 0.0f; accN[k] = 0.0f;
        }
        for (int j = 0; j < nP; j++) {
            float2 t2 = wPxf[j];                 // LDS.64 broadcast
#pragma unroll
            for (int k = 0; k < AR; k++) {
                float d  = xa[k] - t2.x;         // x_a - x_j
                float fd = fa[k] - t2.y;         // f_a - f_j
                float s  = fa[k] + t2.y;         // f_a + f_j > 0
                float r; asm("rcp.approx.f32 %0, %1;" : "=f"(r) : "f"(s));
                float m0 = fmaxf(fd * d, 0.0f);  // relu((fa-fj)*d) ; /s applied after
                acc[k] = fmaf(m0, r, acc[k]);
            }
        }
        for (int j = 0; j < nN; j++) {
            float xj = wNx[j];
#pragma unroll
            for (int k = 0; k < AR; k++)
                accN[k] += fmaxf(xj - xa[k], 0.0f);   // relu(x_j - x_a), C=0
        }
#pragma unroll
        for (int k = 0; k < AR; k++) total += fmaf(GAMMA, accN[k], acc[k]);
    }

    // ---- Tail: AR=1 chunks of 256 (handles cp not multiple of 1024 cheaply)
    for (; abase < cp; abase += TPB) {
        int ai = abase + tid;
        bool ok = ai < cp;
        float xa = ok ? sPx[ai] : 0.0f;
        float fa = ok ? sPf[ai] : 0.0f;
        float acc = 0.0f, accN = 0.0f;
        for (int j = 0; j < nP; j++) {
            float2 t2 = wPxf[j];
            float d = xa - t2.x, fd = fa - t2.y, s = fa + t2.y;
            float r; asm("rcp.approx.f32 %0, %1;" : "=f"(r) : "f"(s));
            acc = fmaf(fmaxf(fd * d, 0.0f), r, acc);
        }
        for (int j = 0; j < nN; j++) accN += fmaxf(wNx[j] - xa, 0.0f);
        if (ok) total += fmaf(GAMMA, accN, acc);
    }

    // ---- Deterministic in-block tree reduction
    red[tid] = total;
    __syncthreads();
    for (int s = TPB / 2; s > 0; s >>= 1) {
        if (tid < s) red[tid] += red[tid + s];
        __syncthreads();
    }
    if (tid == 0) g_partial[b * JT + jt] = red[0];
}

// ---- Fixed-order final reduction over 592 partials (deterministic)
__global__ void reduce_kernel(float* __restrict__ out, int out_size) {
    __shared__ float red[TPB];
    int tid = threadIdx.x;
    float s = 0.0f;
    for (int i = tid; i < BATCH * JT; i += TPB) s += g_partial[i];
    red[tid] = s;
    __syncthreads();
    for (int st = TPB / 2; st > 0; st >>= 1) {
        if (tid < st) red[tid] += red[tid + st];
        __syncthreads();
    }
    if (tid == 0) {
        float r = red[0] / (float)BATCH;
        for (int i = 0; i < out_size; i++) out[i] = r;
    }
}

extern "C" void kernel_launch(void* const* d_in, const int* in_sizes, int n_in,
                              void* d_out, int out_size) {
    const float* inp  = (const float*)d_in[0];   // [16, 2048] f32
    const int*   tgt  = (const int*)d_in[1];     // [16, 2048] i32
    const float* freq = (const float*)d_in[2];   // [2048] f32
    float* out = (float*)d_out;

    pair_kernel<<<dim3(JT, BATCH), TPB>>>(inp, tgt, freq);
    reduce_kernel<<<1, TPB>>>(out, out_size);
}